// round 16
// baseline (speedup 1.0000x reference)
#include <cuda_runtime.h>
#include <cstdint>

#define NN 8192      // nodes
#define DF 128       // feature dim
#define NA 512       // anchors
#define KSEL 32      // k nearest
#define MARGINF 1.0f

#define SCALEQ 16.0f // quant scale: step 1/16; biased-u8 encoding (+128)
#define SLACKQ 64    // prune slack in quant units (= 4.0 real, >> quant noise)
#define QW 32        // packed u8 words per row (128 features)

// distance-kernel tiling
#define TA 32
#define TN 128
#define RA 4
#define RN 4
#define SROWQ 36     // padded smem row stride in words; 144B row = 16B-aligned,
                     // 36%32==4 -> conflict-free uint4 LDS

#define MAXC 1024

// scratch (device globals: allocation-free)
__device__ unsigned g_q[2][NN][QW];                  // packed biased-u8 features (2MB)
__device__ __align__(16) unsigned short g_dq[2][NA][NN];  // quantized distances (16MB)
__device__ float g_rowLoss[2 * NA];
__device__ unsigned int g_done;

// ---------------------------------------------------------------------------
// Kernel I: init (g_done reset) + ncu launch-window alignment.
// ---------------------------------------------------------------------------
__global__ void k_init() {
    if (threadIdx.x == 0) g_done = 0u;
}

// ---------------------------------------------------------------------------
// Kernel 0: quantize both feature matrices to packed biased-u8.
//   u = clamp(round(16*v) + 128, 1, 255); |ua-ub| == |qa-qb| (bias cancels).
// ---------------------------------------------------------------------------
__global__ void k_quant(const float* __restrict__ o1, const float* __restrict__ o2) {
    int idx = blockIdx.x * 256 + threadIdx.x;        // word id in [0, 2*NN*QW)
    const bool second = idx >= NN * QW;
    const float* src = second ? o2 : o1;
    int local = second ? idx - NN * QW : idx;
    float4 v = ((const float4*)src)[local];
    unsigned b0 = (unsigned)max(1, min(255, __float2int_rn(v.x * SCALEQ) + 128));
    unsigned b1 = (unsigned)max(1, min(255, __float2int_rn(v.y * SCALEQ) + 128));
    unsigned b2 = (unsigned)max(1, min(255, __float2int_rn(v.z * SCALEQ) + 128));
    unsigned b3 = (unsigned)max(1, min(255, __float2int_rn(v.w * SCALEQ) + 128));
    (&g_q[0][0][0])[idx] = b0 | (b1 << 8) | (b2 << 16) | (b3 << 24);
}

// ---------------------------------------------------------------------------
// Kernel A: quantized L1 distance matrix via vabsdiffu4 + dp4a.
//   CTA tile 32 anchors x 128 nodes; lane tn handles nodes tn+32j (j=0..3).
//   Per chunk: 8 LDS.128 feed 128 SIMD instructions.
// ---------------------------------------------------------------------------
__global__ __launch_bounds__(256) void k_dist(const int* __restrict__ an1,
                                              const int* __restrict__ an2) {
    __shared__ unsigned sA[TA * SROWQ];
    __shared__ unsigned sN[TN * SROWQ];

    const int side = blockIdx.z;
    const int aT = blockIdx.y;
    const int nT = blockIdx.x;
    const unsigned* __restrict__ aq = side ? &g_q[1][0][0] : &g_q[0][0][0];
    const unsigned* __restrict__ nq = side ? &g_q[0][0][0] : &g_q[1][0][0];
    const int* __restrict__ aidx = side ? an2 : an1;
    const int tid = threadIdx.x;

    for (int i = tid; i < TA * 8; i += 256) {
        int r = i >> 3, c = i & 7;
        int node = aidx[aT * TA + r];
        *(uint4*)&sA[r * SROWQ + c * 4] = *(const uint4*)&aq[node * QW + c * 4];
    }
    for (int i = tid; i < TN * 8; i += 256) {
        int r = i >> 3, c = i & 7;
        *(uint4*)&sN[r * SROWQ + c * 4] = *(const uint4*)&nq[(nT * TN + r) * QW + c * 4];
    }
    __syncthreads();

    const int ta = tid >> 5;
    const int tn = tid & 31;
    unsigned acc[RA][RN];
#pragma unroll
    for (int i = 0; i < RA; i++)
#pragma unroll
        for (int j = 0; j < RN; j++) acc[i][j] = 0u;

    const unsigned* aB = &sA[(ta * RA) * SROWQ];
    const unsigned* nB = &sN[tn * SROWQ];

#pragma unroll
    for (int c = 0; c < 8; c++) {
        uint4 av[RA], nv[RN];
#pragma unroll
        for (int i = 0; i < RA; i++) av[i] = *(const uint4*)&aB[i * SROWQ + c * 4];
#pragma unroll
        for (int j = 0; j < RN; j++) nv[j] = *(const uint4*)&nB[j * 32 * SROWQ + c * 4];
#pragma unroll
        for (int i = 0; i < RA; i++)
#pragma unroll
            for (int j = 0; j < RN; j++) {
                acc[i][j] = __dp4a(__vabsdiffu4(av[i].x, nv[j].x), 0x01010101u, acc[i][j]);
                acc[i][j] = __dp4a(__vabsdiffu4(av[i].y, nv[j].y), 0x01010101u, acc[i][j]);
                acc[i][j] = __dp4a(__vabsdiffu4(av[i].z, nv[j].z), 0x01010101u, acc[i][j]);
                acc[i][j] = __dp4a(__vabsdiffu4(av[i].w, nv[j].w), 0x01010101u, acc[i][j]);
            }
    }

#pragma unroll
    for (int i = 0; i < RA; i++) {
        int A = aT * TA + ta * RA + i;
#pragma unroll
        for (int j = 0; j < RN; j++)
            g_dq[side][A][nT * TN + tn + j * 32] = (unsigned short)acc[i][j];
    }
}

// ---------------------------------------------------------------------------
// Kernel B: prune (quantized) -> exact fp32 recompute of candidates ->
//   exact radix select -> loss. (R12-proven form.)
// ---------------------------------------------------------------------------
__global__ __launch_bounds__(256) void k_topk(const float* __restrict__ out1,
                                              const float* __restrict__ out2,
                                              const int* __restrict__ an1,
                                              const int* __restrict__ an2,
                                              float* __restrict__ outp) {
    const int row = blockIdx.x;                 // 0..1023
    const int side = row >> 9, a = row & (NA - 1);
    const uint4* __restrict__ drow = (const uint4*)&g_dq[side][a][0];  // 1024 x 8 u16
    const int tid = threadIdx.x;
    const int lane = tid & 31, wid = tid >> 5;

    __shared__ unsigned sminq[256];
    __shared__ int cidx[MAXC];
    __shared__ float cd[MAXC];
    __shared__ float sa[DF];
    __shared__ unsigned hist[256];
    __shared__ unsigned wsum[8];
    __shared__ float wpart[8];
    __shared__ float dred[8];
    __shared__ float sfin[256];
    __shared__ int scnt;
    __shared__ unsigned Tqs;
    __shared__ float Dsh;
    __shared__ unsigned selByte, selExc;
    __shared__ unsigned int ticket;

    const float* __restrict__ ab = side ? &out2[(size_t)an2[a] * DF]
                                        : &out1[(size_t)an1[a] * DF];
    const float* __restrict__ nodesf = side ? out1 : out2;

    if (tid < 32) *(float4*)&sa[tid * 4] = *(const float4*)&ab[tid * 4];

    // D[a] = L1(out1[an1[a]], out2[an2[a]]) + margin  (threads 0..127)
    {
        float part = 0.f;
        if (tid < DF) {
            int i1 = an1[a], i2 = an2[a];
            part = fabsf(out1[(size_t)i1 * DF + tid] - out2[(size_t)i2 * DF + tid]);
        }
        for (int o = 16; o; o >>= 1) part += __shfl_xor_sync(0xffffffffu, part, o);
        if (lane == 0) dred[wid] = part;
    }
    if (tid == 0) scnt = 0;

    // pass 1: per-thread quantized minima (SIMD u16 min)
    unsigned mv = 0xFFFFFFFFu;
#pragma unroll
    for (int i = tid; i < NN / 8; i += 256) {
        uint4 w = drow[i];
        mv = __vminu2(mv, __vminu2(__vminu2(w.x, w.y), __vminu2(w.z, w.w)));
    }
    sminq[tid] = min(mv & 0xFFFFu, mv >> 16);
    __syncthreads();
    if (tid == 0) Dsh = dred[0] + dred[1] + dred[2] + dred[3] + MARGINF;

    // T0q = max over 32 disjoint lane-group minima (bound on 32nd smallest)
    if (tid < 32) {
        unsigned gm = sminq[tid];
#pragma unroll
        for (int w = 1; w < 8; w++) gm = min(gm, sminq[w * 32 + tid]);
#pragma unroll
        for (int o = 16; o; o >>= 1) gm = max(gm, __shfl_xor_sync(0xffffffffu, gm, o));
        if (tid == 0) Tqs = gm;
    }
    __syncthreads();
    const unsigned Tq = min(Tqs + SLACKQ, 0xFFFFu);

    // gather candidate indices (quantized value <= Tq), SIMD early-skip
    for (int i = tid; i < NN / 8; i += 256) {
        uint4 w = drow[i];
        unsigned mm = __vminu2(__vminu2(w.x, w.y), __vminu2(w.z, w.w));
        if (min(mm & 0xFFFFu, mm >> 16) > Tq) continue;
        int base = i * 8;
        unsigned h;
        h = w.x & 0xFFFFu; if (h <= Tq) { int p = atomicAdd(&scnt, 1); if (p < MAXC) cidx[p] = base + 0; }
        h = w.x >> 16;     if (h <= Tq) { int p = atomicAdd(&scnt, 1); if (p < MAXC) cidx[p] = base + 1; }
        h = w.y & 0xFFFFu; if (h <= Tq) { int p = atomicAdd(&scnt, 1); if (p < MAXC) cidx[p] = base + 2; }
        h = w.y >> 16;     if (h <= Tq) { int p = atomicAdd(&scnt, 1); if (p < MAXC) cidx[p] = base + 3; }
        h = w.z & 0xFFFFu; if (h <= Tq) { int p = atomicAdd(&scnt, 1); if (p < MAXC) cidx[p] = base + 4; }
        h = w.z >> 16;     if (h <= Tq) { int p = atomicAdd(&scnt, 1); if (p < MAXC) cidx[p] = base + 5; }
        h = w.w & 0xFFFFu; if (h <= Tq) { int p = atomicAdd(&scnt, 1); if (p < MAXC) cidx[p] = base + 6; }
        h = w.w >> 16;     if (h <= Tq) { int p = atomicAdd(&scnt, 1); if (p < MAXC) cidx[p] = base + 7; }
    }
    __syncthreads();
    const int cnt = min(scnt, MAXC);

    // exact fp32 recompute: one warp per candidate (strided)
    for (int c = wid; c < cnt; c += 8) {
        const float* nr = nodesf + (size_t)cidx[c] * DF;
        float4 nv = *(const float4*)&nr[lane * 4];
        float4 av = *(const float4*)&sa[lane * 4];
        float s = fabsf(av.x - nv.x) + fabsf(av.y - nv.y) +
                  fabsf(av.z - nv.z) + fabsf(av.w - nv.w);
#pragma unroll
        for (int o = 16; o; o >>= 1) s += __shfl_xor_sync(0xffffffffu, s, o);
        if (lane == 0) cd[c] = s;
    }
    __syncthreads();

    // radix select: exact 32nd smallest of cd[0..cnt) (positive floats)
    unsigned prefix = 0;
    unsigned target = KSEL;
    unsigned below = 0;
#pragma unroll
    for (int p = 3; p >= 0; --p) {
        const int shift = p * 8;
        hist[tid] = 0;
        __syncthreads();
        for (int i = tid; i < cnt; i += 256) {
            unsigned u = __float_as_uint(cd[i]);
            bool match = (p == 3) || ((u >> (shift + 8)) == (prefix >> (shift + 8)));
            if (match) atomicAdd(&hist[(u >> shift) & 0xFFu], 1u);
        }
        __syncthreads();
        unsigned h = hist[tid];
        unsigned inc = h;
#pragma unroll
        for (int o = 1; o < 32; o <<= 1) {
            unsigned n = __shfl_up_sync(0xffffffffu, inc, o);
            if (lane >= o) inc += n;
        }
        if (lane == 31) wsum[wid] = inc;
        __syncthreads();
        unsigned woff = 0;
        for (int w = 0; w < wid; w++) woff += wsum[w];
        inc += woff;
        unsigned exc = inc - h;
        if (exc < target && target <= inc) { selByte = (unsigned)tid; selExc = exc; }
        __syncthreads();
        prefix |= (selByte << shift);
        target -= selExc;
        below += selExc;
        __syncthreads();
    }
    const float Tval = __uint_as_float(prefix);
    const float Dv = Dsh;

    // loss = sum_{v<T} relu(D-v) + (32-below)*relu(D-T)
    float part = 0.f;
    for (int i = tid; i < cnt; i += 256) {
        float v = cd[i];
        if (v < Tval) part += fmaxf(Dv - v, 0.f);
    }
#pragma unroll
    for (int o = 16; o; o >>= 1) part += __shfl_xor_sync(0xffffffffu, part, o);
    if (lane == 0) wpart[wid] = part;
    __syncthreads();
    if (tid == 0) {
        float loss = 0.f;
#pragma unroll
        for (int w = 0; w < 8; w++) loss += wpart[w];
        loss += (float)(KSEL - (int)below) * fmaxf(Dv - Tval, 0.f);
        g_rowLoss[row] = loss;
        __threadfence();
        ticket = atomicAdd(&g_done, 1u);
    }
    __syncthreads();

    // last block: deterministic final reduction
    if (ticket == 2 * NA - 1) {
        float s = g_rowLoss[tid] + g_rowLoss[tid + 256] +
                  g_rowLoss[tid + 512] + g_rowLoss[tid + 768];
        sfin[tid] = s;
        __syncthreads();
        for (int x = 128; x > 0; x >>= 1) {
            if (tid < x) sfin[tid] += sfin[tid + x];
            __syncthreads();
        }
        if (tid == 0) outp[0] = sfin[0] / (float)(NA * KSEL);
    }
}

// ---------------------------------------------------------------------------
extern "C" void kernel_launch(void* const* d_in, const int* in_sizes, int n_in,
                              void* d_out, int out_size) {
    const float* out1 = (const float*)d_in[0];
    const float* out2 = (const float*)d_in[1];
    const int* an1 = (const int*)d_in[2];
    const int* an2 = (const int*)d_in[3];
    float* out = (float*)d_out;

    k_init<<<1, 32>>>();
    k_quant<<<2 * NN * QW / 256, 256>>>(out1, out2);
    dim3 g(NN / TN, NA / TA, 2);
    k_dist<<<g, 256>>>(an1, an2);
    k_topk<<<2 * NA, 256>>>(out1, out2, an1, an2, out);
}

// round 17
// speedup vs baseline: 1.2272x; 1.2272x over previous
#include <cuda_runtime.h>
#include <cstdint>

#define NN 8192      // nodes
#define DF 128       // feature dim
#define NA 512       // anchors
#define KSEL 32      // k nearest
#define MARGINF 1.0f

#define SCALEQ 16.0f // quant scale: step 1/16; biased-u8 encoding (+128)
#define SLACKQ 24    // prune slack in quant units (~3.6 sigma of pair quant noise)
#define QW 32        // packed u8 words per row (128 features)

// distance-kernel tiling (R12 proven shape)
#define TA 32
#define TN 64
#define RA 4
#define RN 2
#define SROWQ 36     // padded smem row stride in words; 144B row, conflict-free

#define MAXC 1024

// scratch (device globals: allocation-free)
__device__ unsigned g_q[2][NN][QW];                  // packed biased-u8 features (2MB)
__device__ __align__(16) unsigned short g_dq[2][NA][NN];  // quantized distances (16MB)
__device__ float g_rowLoss[2 * NA];
__device__ unsigned int g_done;

// ---------------------------------------------------------------------------
// Kernel 0: quantize both feature matrices to packed biased-u8 (+g_done reset).
//   u = clamp(round(16*v) + 128, 1, 255); |ua-ub| == |qa-qb| (bias cancels).
// ---------------------------------------------------------------------------
__global__ void k_quant(const float* __restrict__ o1, const float* __restrict__ o2) {
    int idx = blockIdx.x * 256 + threadIdx.x;        // word id in [0, 2*NN*QW)
    if (idx == 0) g_done = 0u;
    const bool second = idx >= NN * QW;
    const float* src = second ? o2 : o1;
    int local = second ? idx - NN * QW : idx;
    float4 v = ((const float4*)src)[local];
    unsigned b0 = (unsigned)max(1, min(255, __float2int_rn(v.x * SCALEQ) + 128));
    unsigned b1 = (unsigned)max(1, min(255, __float2int_rn(v.y * SCALEQ) + 128));
    unsigned b2 = (unsigned)max(1, min(255, __float2int_rn(v.z * SCALEQ) + 128));
    unsigned b3 = (unsigned)max(1, min(255, __float2int_rn(v.w * SCALEQ) + 128));
    (&g_q[0][0][0])[idx] = b0 | (b1 << 8) | (b2 << 16) | (b3 << 24);
}

// ---------------------------------------------------------------------------
// Kernel A: quantized L1 distance matrix via vabsdiffu4 + dp4a.
//   __launch_bounds__(256,4): cap regs ~64 -> 4 CTAs/SM for latency hiding.
//   unroll 2 keeps live staging registers low.
// ---------------------------------------------------------------------------
__global__ __launch_bounds__(256, 4) void k_dist(const int* __restrict__ an1,
                                                 const int* __restrict__ an2) {
    __shared__ unsigned sA[TA * SROWQ];
    __shared__ unsigned sN[TN * SROWQ];

    const int side = blockIdx.z;
    const int aT = blockIdx.y;
    const int nT = blockIdx.x;
    const unsigned* __restrict__ aq = side ? &g_q[1][0][0] : &g_q[0][0][0];
    const unsigned* __restrict__ nq = side ? &g_q[0][0][0] : &g_q[1][0][0];
    const int* __restrict__ aidx = side ? an2 : an1;
    const int tid = threadIdx.x;

    for (int i = tid; i < TA * 8; i += 256) {
        int r = i >> 3, c = i & 7;
        int node = aidx[aT * TA + r];
        *(uint4*)&sA[r * SROWQ + c * 4] = *(const uint4*)&aq[node * QW + c * 4];
    }
    for (int i = tid; i < TN * 8; i += 256) {
        int r = i >> 3, c = i & 7;
        *(uint4*)&sN[r * SROWQ + c * 4] = *(const uint4*)&nq[(nT * TN + r) * QW + c * 4];
    }
    __syncthreads();

    const int ta = tid >> 5;
    const int tn = tid & 31;
    unsigned acc[RA][RN];
#pragma unroll
    for (int i = 0; i < RA; i++)
#pragma unroll
        for (int j = 0; j < RN; j++) acc[i][j] = 0u;

    const unsigned* aB = &sA[(ta * RA) * SROWQ];
    const unsigned* nB = &sN[tn * SROWQ];

#pragma unroll 2
    for (int c = 0; c < 8; c++) {
        uint4 av[RA], nv[RN];
#pragma unroll
        for (int i = 0; i < RA; i++) av[i] = *(const uint4*)&aB[i * SROWQ + c * 4];
#pragma unroll
        for (int j = 0; j < RN; j++) nv[j] = *(const uint4*)&nB[j * 32 * SROWQ + c * 4];
#pragma unroll
        for (int i = 0; i < RA; i++)
#pragma unroll
            for (int j = 0; j < RN; j++) {
                acc[i][j] = __dp4a(__vabsdiffu4(av[i].x, nv[j].x), 0x01010101u, acc[i][j]);
                acc[i][j] = __dp4a(__vabsdiffu4(av[i].y, nv[j].y), 0x01010101u, acc[i][j]);
                acc[i][j] = __dp4a(__vabsdiffu4(av[i].z, nv[j].z), 0x01010101u, acc[i][j]);
                acc[i][j] = __dp4a(__vabsdiffu4(av[i].w, nv[j].w), 0x01010101u, acc[i][j]);
            }
    }

#pragma unroll
    for (int i = 0; i < RA; i++) {
        int A = aT * TA + ta * RA + i;
#pragma unroll
        for (int j = 0; j < RN; j++)
            g_dq[side][A][nT * TN + tn + j * 32] = (unsigned short)acc[i][j];
    }
}

// ---------------------------------------------------------------------------
// Kernel B: prune (quantized) -> exact fp32 recompute of candidates ->
//   exact radix select -> loss. (R12-proven form, tighter slack.)
// ---------------------------------------------------------------------------
__global__ __launch_bounds__(256) void k_topk(const float* __restrict__ out1,
                                              const float* __restrict__ out2,
                                              const int* __restrict__ an1,
                                              const int* __restrict__ an2,
                                              float* __restrict__ outp) {
    const int row = blockIdx.x;                 // 0..1023
    const int side = row >> 9, a = row & (NA - 1);
    const uint4* __restrict__ drow = (const uint4*)&g_dq[side][a][0];  // 1024 x 8 u16
    const int tid = threadIdx.x;
    const int lane = tid & 31, wid = tid >> 5;

    __shared__ unsigned sminq[256];
    __shared__ int cidx[MAXC];
    __shared__ float cd[MAXC];
    __shared__ float sa[DF];
    __shared__ unsigned hist[256];
    __shared__ unsigned wsum[8];
    __shared__ float wpart[8];
    __shared__ float dred[8];
    __shared__ float sfin[256];
    __shared__ int scnt;
    __shared__ unsigned Tqs;
    __shared__ float Dsh;
    __shared__ unsigned selByte, selExc;
    __shared__ unsigned int ticket;

    const float* __restrict__ ab = side ? &out2[(size_t)an2[a] * DF]
                                        : &out1[(size_t)an1[a] * DF];
    const float* __restrict__ nodesf = side ? out1 : out2;

    if (tid < 32) *(float4*)&sa[tid * 4] = *(const float4*)&ab[tid * 4];

    // D[a] = L1(out1[an1[a]], out2[an2[a]]) + margin  (threads 0..127)
    {
        float part = 0.f;
        if (tid < DF) {
            int i1 = an1[a], i2 = an2[a];
            part = fabsf(out1[(size_t)i1 * DF + tid] - out2[(size_t)i2 * DF + tid]);
        }
        for (int o = 16; o; o >>= 1) part += __shfl_xor_sync(0xffffffffu, part, o);
        if (lane == 0) dred[wid] = part;
    }
    if (tid == 0) scnt = 0;

    // pass 1: per-thread quantized minima (SIMD u16 min)
    unsigned mv = 0xFFFFFFFFu;
#pragma unroll
    for (int i = tid; i < NN / 8; i += 256) {
        uint4 w = drow[i];
        mv = __vminu2(mv, __vminu2(__vminu2(w.x, w.y), __vminu2(w.z, w.w)));
    }
    sminq[tid] = min(mv & 0xFFFFu, mv >> 16);
    __syncthreads();
    if (tid == 0) Dsh = dred[0] + dred[1] + dred[2] + dred[3] + MARGINF;

    // T0q = max over 32 disjoint lane-group minima (bound on 32nd smallest)
    if (tid < 32) {
        unsigned gm = sminq[tid];
#pragma unroll
        for (int w = 1; w < 8; w++) gm = min(gm, sminq[w * 32 + tid]);
#pragma unroll
        for (int o = 16; o; o >>= 1) gm = max(gm, __shfl_xor_sync(0xffffffffu, gm, o));
        if (tid == 0) Tqs = gm;
    }
    __syncthreads();
    const unsigned Tq = min(Tqs + SLACKQ, 0xFFFFu);

    // gather candidate indices (quantized value <= Tq), SIMD early-skip
    for (int i = tid; i < NN / 8; i += 256) {
        uint4 w = drow[i];
        unsigned mm = __vminu2(__vminu2(w.x, w.y), __vminu2(w.z, w.w));
        if (min(mm & 0xFFFFu, mm >> 16) > Tq) continue;
        int base = i * 8;
        unsigned h;
        h = w.x & 0xFFFFu; if (h <= Tq) { int p = atomicAdd(&scnt, 1); if (p < MAXC) cidx[p] = base + 0; }
        h = w.x >> 16;     if (h <= Tq) { int p = atomicAdd(&scnt, 1); if (p < MAXC) cidx[p] = base + 1; }
        h = w.y & 0xFFFFu; if (h <= Tq) { int p = atomicAdd(&scnt, 1); if (p < MAXC) cidx[p] = base + 2; }
        h = w.y >> 16;     if (h <= Tq) { int p = atomicAdd(&scnt, 1); if (p < MAXC) cidx[p] = base + 3; }
        h = w.z & 0xFFFFu; if (h <= Tq) { int p = atomicAdd(&scnt, 1); if (p < MAXC) cidx[p] = base + 4; }
        h = w.z >> 16;     if (h <= Tq) { int p = atomicAdd(&scnt, 1); if (p < MAXC) cidx[p] = base + 5; }
        h = w.w & 0xFFFFu; if (h <= Tq) { int p = atomicAdd(&scnt, 1); if (p < MAXC) cidx[p] = base + 6; }
        h = w.w >> 16;     if (h <= Tq) { int p = atomicAdd(&scnt, 1); if (p < MAXC) cidx[p] = base + 7; }
    }
    __syncthreads();
    const int cnt = min(scnt, MAXC);

    // exact fp32 recompute: one warp per candidate (strided)
    for (int c = wid; c < cnt; c += 8) {
        const float* nr = nodesf + (size_t)cidx[c] * DF;
        float4 nv = *(const float4*)&nr[lane * 4];
        float4 av = *(const float4*)&sa[lane * 4];
        float s = fabsf(av.x - nv.x) + fabsf(av.y - nv.y) +
                  fabsf(av.z - nv.z) + fabsf(av.w - nv.w);
#pragma unroll
        for (int o = 16; o; o >>= 1) s += __shfl_xor_sync(0xffffffffu, s, o);
        if (lane == 0) cd[c] = s;
    }
    __syncthreads();

    // radix select: exact 32nd smallest of cd[0..cnt) (positive floats)
    unsigned prefix = 0;
    unsigned target = KSEL;
    unsigned below = 0;
#pragma unroll
    for (int p = 3; p >= 0; --p) {
        const int shift = p * 8;
        hist[tid] = 0;
        __syncthreads();
        for (int i = tid; i < cnt; i += 256) {
            unsigned u = __float_as_uint(cd[i]);
            bool match = (p == 3) || ((u >> (shift + 8)) == (prefix >> (shift + 8)));
            if (match) atomicAdd(&hist[(u >> shift) & 0xFFu], 1u);
        }
        __syncthreads();
        unsigned h = hist[tid];
        unsigned inc = h;
#pragma unroll
        for (int o = 1; o < 32; o <<= 1) {
            unsigned n = __shfl_up_sync(0xffffffffu, inc, o);
            if (lane >= o) inc += n;
        }
        if (lane == 31) wsum[wid] = inc;
        __syncthreads();
        unsigned woff = 0;
        for (int w = 0; w < wid; w++) woff += wsum[w];
        inc += woff;
        unsigned exc = inc - h;
        if (exc < target && target <= inc) { selByte = (unsigned)tid; selExc = exc; }
        __syncthreads();
        prefix |= (selByte << shift);
        target -= selExc;
        below += selExc;
        __syncthreads();
    }
    const float Tval = __uint_as_float(prefix);
    const float Dv = Dsh;

    // loss = sum_{v<T} relu(D-v) + (32-below)*relu(D-T)
    float part = 0.f;
    for (int i = tid; i < cnt; i += 256) {
        float v = cd[i];
        if (v < Tval) part += fmaxf(Dv - v, 0.f);
    }
#pragma unroll
    for (int o = 16; o; o >>= 1) part += __shfl_xor_sync(0xffffffffu, part, o);
    if (lane == 0) wpart[wid] = part;
    __syncthreads();
    if (tid == 0) {
        float loss = 0.f;
#pragma unroll
        for (int w = 0; w < 8; w++) loss += wpart[w];
        loss += (float)(KSEL - (int)below) * fmaxf(Dv - Tval, 0.f);
        g_rowLoss[row] = loss;
        __threadfence();
        ticket = atomicAdd(&g_done, 1u);
    }
    __syncthreads();

    // last block: deterministic final reduction
    if (ticket == 2 * NA - 1) {
        float s = g_rowLoss[tid] + g_rowLoss[tid + 256] +
                  g_rowLoss[tid + 512] + g_rowLoss[tid + 768];
        sfin[tid] = s;
        __syncthreads();
        for (int x = 128; x > 0; x >>= 1) {
            if (tid < x) sfin[tid] += sfin[tid + x];
            __syncthreads();
        }
        if (tid == 0) outp[0] = sfin[0] / (float)(NA * KSEL);
    }
}

// ---------------------------------------------------------------------------
extern "C" void kernel_launch(void* const* d_in, const int* in_sizes, int n_in,
                              void* d_out, int out_size) {
    const float* out1 = (const float*)d_in[0];
    const float* out2 = (const float*)d_in[1];
    const int* an1 = (const int*)d_in[2];
    const int* an2 = (const int*)d_in[3];
    float* out = (float*)d_out;

    k_quant<<<2 * NN * QW / 256, 256>>>(out1, out2);
    dim3 g(NN / TN, NA / TA, 2);
    k_dist<<<g, 256>>>(an1, an2);
    k_topk<<<2 * NA, 256>>>(out1, out2, an1, an2, out);
}